// round 2
// baseline (speedup 1.0000x reference)
#include <cuda_runtime.h>
#include <math.h>

// Problem constants
#define Bv   4
#define Nv   4096
#define Cv   1024
#define Hv   16
#define Dv   64
#define BSv  64
#define NBv  64
#define Mv   (Bv * Nv)   // 16384 rows

// Scratch (device globals: allowed; cudaMalloc is not).
// g_Q doubles as the attention-output buffer: CTA (b,h,nb) writes only
// columns [h*64, h*64+64) of rows [b*N+nb*64, +64), which it alone reads
// for those columns (other heads' CTAs touch disjoint column ranges).
__device__ float g_Q[(size_t)Mv * Cv];
__device__ float g_K[(size_t)Mv * Cv];
__device__ float g_V[(size_t)Mv * Cv];

// ---------------------------------------------------------------------------
// GEMM: Y[m, n] = sum_k X[m, k] * W[n, k] + bias[n]
// X: [Mv, Cv] row-major, W: [Cv, Cv] row-major (out, in), Y: [Mv, Cv]
// 128x128 tile, K-step 16, 256 threads, 8x8 register microtile.
// ---------------------------------------------------------------------------
#define GTM 128
#define GTN 128
#define GTK 16
#define GS  132   // smem row stride (pad; multiple of 4 for float4)

__global__ __launch_bounds__(256) void gemm_nt_bias(
    const float* __restrict__ X, const float* __restrict__ W,
    const float* __restrict__ bias, float* __restrict__ Y)
{
    __shared__ __align__(16) float Xs[GTK][GS];
    __shared__ __align__(16) float Ws[GTK][GS];

    const int tid = threadIdx.x;
    const int tx = tid & 15;       // n-group
    const int ty = tid >> 4;       // m-group
    const int m0 = blockIdx.y * GTM;
    const int n0 = blockIdx.x * GTN;

    const float* Xbase = X + (size_t)m0 * Cv;
    const float* Wbase = W + (size_t)n0 * Cv;

    float acc[8][8];
#pragma unroll
    for (int i = 0; i < 8; i++)
#pragma unroll
        for (int j = 0; j < 8; j++) acc[i][j] = 0.f;

    for (int k0 = 0; k0 < Cv; k0 += GTK) {
#pragma unroll
        for (int l = 0; l < 2; l++) {
            int lin = tid + l * 256;      // 0..511
            int r   = lin >> 2;           // 0..127
            int cv  = (lin & 3) * 4;      // 0,4,8,12
            float4 vx = *(const float4*)(Xbase + (size_t)r * Cv + k0 + cv);
            Xs[cv + 0][r] = vx.x; Xs[cv + 1][r] = vx.y;
            Xs[cv + 2][r] = vx.z; Xs[cv + 3][r] = vx.w;
            float4 vw = *(const float4*)(Wbase + (size_t)r * Cv + k0 + cv);
            Ws[cv + 0][r] = vw.x; Ws[cv + 1][r] = vw.y;
            Ws[cv + 2][r] = vw.z; Ws[cv + 3][r] = vw.w;
        }
        __syncthreads();

#pragma unroll
        for (int kk = 0; kk < GTK; kk++) {
            float a[8], bb[8];
            *(float4*)&a[0]  = *(const float4*)&Xs[kk][ty * 8];
            *(float4*)&a[4]  = *(const float4*)&Xs[kk][ty * 8 + 4];
            *(float4*)&bb[0] = *(const float4*)&Ws[kk][tx * 8];
            *(float4*)&bb[4] = *(const float4*)&Ws[kk][tx * 8 + 4];
#pragma unroll
            for (int i = 0; i < 8; i++)
#pragma unroll
                for (int j = 0; j < 8; j++)
                    acc[i][j] += a[i] * bb[j];
        }
        __syncthreads();
    }

    float bvals[8];
#pragma unroll
    for (int j = 0; j < 8; j++) bvals[j] = bias[n0 + tx * 8 + j];

#pragma unroll
    for (int i = 0; i < 8; i++) {
        float* yrow = Y + (size_t)(m0 + ty * 8 + i) * Cv + n0 + tx * 8;
        float4 o1 = make_float4(acc[i][0] + bvals[0], acc[i][1] + bvals[1],
                                acc[i][2] + bvals[2], acc[i][3] + bvals[3]);
        float4 o2 = make_float4(acc[i][4] + bvals[4], acc[i][5] + bvals[5],
                                acc[i][6] + bvals[6], acc[i][7] + bvals[7]);
        *(float4*)(yrow)     = o1;
        *(float4*)(yrow + 4) = o2;
    }
}

// ---------------------------------------------------------------------------
// Block-sparse attention. One CTA per (query block, head, batch).
// Effective window: [prev block (if any), self block]; the next block is
// always fully removed by the causal mask (64+i >= j requires i >= 64 for
// j >= 128). Valid keys per row i are the contiguous range [start, 64+i].
// Reads Q from QO and writes its output back into QO (disjoint columns per
// head; each CTA snapshots its own Q tile into smem before any O write).
// ---------------------------------------------------------------------------
#define SP 132   // S row stride (128 cols + pad, mult of 4)
#define KP 68    // K/V smem stride (64 + pad, mult of 4)

#define ATTN_SMEM_FLOATS (64 * 64 + 64 * SP + 64 * KP)
#define ATTN_SMEM_BYTES  (ATTN_SMEM_FLOATS * 4)

__global__ __launch_bounds__(256) void attn_kernel(
    float* __restrict__ QO, const float* __restrict__ K,
    const float* __restrict__ V)
{
    extern __shared__ __align__(16) float sm[];
    float* Qs  = sm;                 // [64][64]  q row-major
    float* Ss  = Qs + 64 * 64;       // [64][SP]  scores
    float* KVs = Ss + 64 * SP;       // [64][KP]  K^T (d-major) then V (k-major)

    const int tid = threadIdx.x;
    const int nb = blockIdx.x, h = blockIdx.y, b = blockIdx.z;
    const int qrow0 = b * Nv + nb * BSv;
    const int col0  = h * Dv;

    // Load Q tile (64x64), row-major
#pragma unroll
    for (int l = 0; l < 4; l++) {
        int lin = tid + l * 256;      // 0..1023
        int r   = lin >> 4;
        int c   = (lin & 15) * 4;
        *(float4*)&Qs[r * 64 + c] =
            *(const float4*)(QO + (size_t)(qrow0 + r) * Cv + col0 + c);
    }

    const int tq = tid >> 4, tk = tid & 15;
    const int q0 = tq * 4;
    const float scale = 0.125f;   // d^-0.5, d=64

    // ---- scores: S[q, w*64+k] = scale * Q[q,:] . K[k,:]
    for (int w = 0; w < 2; w++) {
        int kb = nb - 1 + w;
        if (kb < 0) continue;
        int krow0 = b * Nv + kb * BSv;
        __syncthreads();   // Q visible; previous KVs readers done
        // load K transposed: KVs[d][k]
#pragma unroll
        for (int l = 0; l < 4; l++) {
            int lin = tid + l * 256;
            int r   = lin >> 4;
            int c   = (lin & 15) * 4;
            float4 v = *(const float4*)(K + (size_t)(krow0 + r) * Cv + col0 + c);
            KVs[(c + 0) * KP + r] = v.x;
            KVs[(c + 1) * KP + r] = v.y;
            KVs[(c + 2) * KP + r] = v.z;
            KVs[(c + 3) * KP + r] = v.w;
        }
        __syncthreads();

        float acc[4][4] = {};
        int k0 = tk * 4;
#pragma unroll 8
        for (int dd = 0; dd < 64; dd++) {
            float4 kv = *(const float4*)&KVs[dd * KP + k0];
            float a0 = Qs[(q0 + 0) * 64 + dd];
            float a1 = Qs[(q0 + 1) * 64 + dd];
            float a2 = Qs[(q0 + 2) * 64 + dd];
            float a3 = Qs[(q0 + 3) * 64 + dd];
            acc[0][0] += a0 * kv.x; acc[0][1] += a0 * kv.y;
            acc[0][2] += a0 * kv.z; acc[0][3] += a0 * kv.w;
            acc[1][0] += a1 * kv.x; acc[1][1] += a1 * kv.y;
            acc[1][2] += a1 * kv.z; acc[1][3] += a1 * kv.w;
            acc[2][0] += a2 * kv.x; acc[2][1] += a2 * kv.y;
            acc[2][2] += a2 * kv.z; acc[2][3] += a2 * kv.w;
            acc[3][0] += a3 * kv.x; acc[3][1] += a3 * kv.y;
            acc[3][2] += a3 * kv.z; acc[3][3] += a3 * kv.w;
        }
#pragma unroll
        for (int i = 0; i < 4; i++) {
            *(float4*)&Ss[(q0 + i) * SP + w * 64 + k0] =
                make_float4(acc[i][0] * scale, acc[i][1] * scale,
                            acc[i][2] * scale, acc[i][3] * scale);
        }
    }
    __syncthreads();

    // ---- softmax per row; valid key range is contiguous [jstart, 64+i]
    if (tid < 64) {
        int i = tid;
        int jstart = (nb > 0) ? 0 : 64;
        int jend   = 64 + i;            // inclusive
        float* row = &Ss[i * SP];
        for (int j = jend + 1; j < 128; j++) row[j] = 0.f;  // causal tail -> p=0
        float m = -1e30f;
        for (int j = jstart; j <= jend; j++) m = fmaxf(m, row[j]);
        float s = 0.f;
        for (int j = jstart; j <= jend; j++) {
            float e = __expf(row[j] - m);
            row[j] = e;
            s += e;
        }
        float inv = 1.f / s;
        for (int j = jstart; j <= jend; j++) row[j] *= inv;
    }

    // ---- O = P @ V
    float oacc[4][4] = {};
    const int d0 = tk * 4;
    for (int w = 0; w < 2; w++) {
        int kb = nb - 1 + w;
        if (kb < 0) continue;
        int krow0 = b * Nv + kb * BSv;
        __syncthreads();   // softmax done; previous KVs readers done
        // load V row-major: KVs[k][d]
#pragma unroll
        for (int l = 0; l < 4; l++) {
            int lin = tid + l * 256;
            int r   = lin >> 4;
            int c   = (lin & 15) * 4;
            *(float4*)&KVs[r * KP + c] =
                *(const float4*)(V + (size_t)(krow0 + r) * Cv + col0 + c);
        }
        __syncthreads();

#pragma unroll 4
        for (int k = 0; k < 64; k++) {
            float4 vv = *(const float4*)&KVs[k * KP + d0];
            float p0 = Ss[(q0 + 0) * SP + w * 64 + k];
            float p1 = Ss[(q0 + 1) * SP + w * 64 + k];
            float p2 = Ss[(q0 + 2) * SP + w * 64 + k];
            float p3 = Ss[(q0 + 3) * SP + w * 64 + k];
            oacc[0][0] += p0 * vv.x; oacc[0][1] += p0 * vv.y;
            oacc[0][2] += p0 * vv.z; oacc[0][3] += p0 * vv.w;
            oacc[1][0] += p1 * vv.x; oacc[1][1] += p1 * vv.y;
            oacc[1][2] += p1 * vv.z; oacc[1][3] += p1 * vv.w;
            oacc[2][0] += p2 * vv.x; oacc[2][1] += p2 * vv.y;
            oacc[2][2] += p2 * vv.z; oacc[2][3] += p2 * vv.w;
            oacc[3][0] += p3 * vv.x; oacc[3][1] += p3 * vv.y;
            oacc[3][2] += p3 * vv.z; oacc[3][3] += p3 * vv.w;
        }
    }

#pragma unroll
    for (int i = 0; i < 4; i++) {
        *(float4*)(QO + (size_t)(qrow0 + q0 + i) * Cv + col0 + d0) =
            make_float4(oacc[i][0], oacc[i][1], oacc[i][2], oacc[i][3]);
    }
}

// ---------------------------------------------------------------------------
extern "C" void kernel_launch(void* const* d_in, const int* in_sizes, int n_in,
                              void* d_out, int out_size)
{
    const float* x  = (const float*)d_in[0];
    const float* Wq = (const float*)d_in[1];
    const float* bq = (const float*)d_in[2];
    const float* Wk = (const float*)d_in[3];
    const float* bk = (const float*)d_in[4];
    const float* Wv = (const float*)d_in[5];
    const float* bv = (const float*)d_in[6];
    const float* Wo = (const float*)d_in[7];
    const float* bo = (const float*)d_in[8];
    float* out = (float*)d_out;

    void *qp, *kp, *vp;
    cudaGetSymbolAddress(&qp, g_Q);
    cudaGetSymbolAddress(&kp, g_K);
    cudaGetSymbolAddress(&vp, g_V);
    float* Qp = (float*)qp;
    float* Kp = (float*)kp;
    float* Vp = (float*)vp;

    cudaFuncSetAttribute(attn_kernel,
                         cudaFuncAttributeMaxDynamicSharedMemorySize,
                         ATTN_SMEM_BYTES);

    dim3 gg(Cv / GTN, Mv / GTM);   // (8, 128)
    gemm_nt_bias<<<gg, 256>>>(x, Wq, bq, Qp);
    gemm_nt_bias<<<gg, 256>>>(x, Wk, bk, Kp);
    gemm_nt_bias<<<gg, 256>>>(x, Wv, bv, Vp);

    dim3 ga(NBv, Hv, Bv);
    attn_kernel<<<ga, 256, ATTN_SMEM_BYTES>>>(Qp, Kp, Vp);

    gemm_nt_bias<<<gg, 256>>>(Qp, Wo, bo, out);
}

// round 5
// speedup vs baseline: 2.2263x; 2.2263x over previous
#include <cuda_runtime.h>
#include <cuda_bf16.h>
#include <cstdint>
#include <math.h>

// Problem constants
#define Bv   4
#define Nv   4096
#define Cv   1024
#define Hv   16
#define Dv   64
#define BSv  64
#define NBv  64
#define Mv   (Bv * Nv)   // 16384 rows

// ---------------------------------------------------------------------------
// Scratch (device globals; no runtime allocation allowed)
// ---------------------------------------------------------------------------
__device__ float g_Q[(size_t)Mv * Cv];   // Q, then attention output (disjoint head cols)
__device__ float g_K[(size_t)Mv * Cv];
__device__ float g_V[(size_t)Mv * Cv];
__device__ __nv_bfloat16 g_Xhi[(size_t)Mv * Cv];
__device__ __nv_bfloat16 g_Xlo[(size_t)Mv * Cv];
__device__ __nv_bfloat16 g_Ohi[(size_t)Mv * Cv];
__device__ __nv_bfloat16 g_Olo[(size_t)Mv * Cv];
__device__ __nv_bfloat16 g_Whi[4 * (size_t)Cv * Cv];
__device__ __nv_bfloat16 g_Wlo[4 * (size_t)Cv * Cv];

__device__ __forceinline__ uint32_t smem_u32(const void* p) {
    return (uint32_t)__cvta_generic_to_shared(p);
}

__device__ __forceinline__ void cp16(uint32_t saddr, const void* gaddr) {
    asm volatile("cp.async.cg.shared.global [%0], [%1], 16;"
                 :: "r"(saddr), "l"(gaddr));
}

// ---------------------------------------------------------------------------
// Split: fp32 -> bf16 hi + bf16 lo (lo = bf16(x - float(hi)))
// ---------------------------------------------------------------------------
__global__ __launch_bounds__(256) void split_kernel(
    const float* __restrict__ src, __nv_bfloat16* __restrict__ hi,
    __nv_bfloat16* __restrict__ lo, int n4)
{
    int i = blockIdx.x * blockDim.x + threadIdx.x;
    if (i >= n4) return;
    float4 v = *(const float4*)(src + (size_t)i * 4);
    __nv_bfloat16 h0 = __float2bfloat16(v.x);
    __nv_bfloat16 h1 = __float2bfloat16(v.y);
    __nv_bfloat16 h2 = __float2bfloat16(v.z);
    __nv_bfloat16 h3 = __float2bfloat16(v.w);
    __nv_bfloat16 l0 = __float2bfloat16(v.x - __bfloat162float(h0));
    __nv_bfloat16 l1 = __float2bfloat16(v.y - __bfloat162float(h1));
    __nv_bfloat16 l2 = __float2bfloat16(v.z - __bfloat162float(h2));
    __nv_bfloat16 l3 = __float2bfloat16(v.w - __bfloat162float(h3));
    __nv_bfloat162 hv0 = __nv_bfloat162(h0, h1), hv1 = __nv_bfloat162(h2, h3);
    __nv_bfloat162 lv0 = __nv_bfloat162(l0, l1), lv1 = __nv_bfloat162(l2, l3);
    uint2 hp, lp;
    hp.x = *(uint32_t*)&hv0; hp.y = *(uint32_t*)&hv1;
    lp.x = *(uint32_t*)&lv0; lp.y = *(uint32_t*)&lv1;
    *(uint2*)(hi + (size_t)i * 4) = hp;
    *(uint2*)(lo + (size_t)i * 4) = lp;
}

// ---------------------------------------------------------------------------
// HMMA GEMM: Y[m,n] = sum_k A[m,k]*B[n,k] + bias[n], split-bf16 3-product.
// mma.sync m16n8k16 (base PTX ISA — compute_103-safe).
// CTA 128x128, 8 warps each 64x32. 2-stage cp.async pipeline, K-chunk 64.
// Smem tiles padded to 72 bf16/row (144 B) for conflict-free ldmatrix.
// ---------------------------------------------------------------------------
#define CHUNKS   16
#define RSB      144                       // row stride bytes (72 bf16)
#define TILE_B   (128 * RSB)               // 18432
#define STAGE_B  (4 * TILE_B)              // 73728
#define GEMM_SMEM (2 * STAGE_B)            // 147456

__global__ __launch_bounds__(256, 1) void gemm_mma(
    const __nv_bfloat16* __restrict__ Ahi, const __nv_bfloat16* __restrict__ Alo,
    const __nv_bfloat16* __restrict__ Bhi, const __nv_bfloat16* __restrict__ Blo,
    const float* __restrict__ bias, float* __restrict__ Y)
{
    extern __shared__ __align__(16) char smem[];

    const int tid   = threadIdx.x;
    const int lane  = tid & 31;
    const int wid   = tid >> 5;
    const int warp_m = wid >> 2;     // 0..1
    const int warp_n = wid & 3;      // 0..3
    const int n0 = blockIdx.x * 128;
    const int m0 = blockIdx.y * 128;

    const __nv_bfloat16* srcs[4] = {
        Ahi + (size_t)m0 * Cv, Alo + (size_t)m0 * Cv,
        Bhi + (size_t)n0 * Cv, Blo + (size_t)n0 * Cv };

    const uint32_t sb = smem_u32(smem);

    // acc[mi][ni][4] : 4 m16 tiles x 4 n8 tiles per warp
    float acc[4][4][4];
#pragma unroll
    for (int mi = 0; mi < 4; mi++)
#pragma unroll
        for (int ni = 0; ni < 4; ni++)
#pragma unroll
            for (int f = 0; f < 4; f++) acc[mi][ni][f] = 0.f;

    auto load_stage = [&](int c, int s) {
        const int k0 = c * 64;
        const uint32_t base = sb + s * STAGE_B;
#pragma unroll
        for (int j = 0; j < 16; j++) {
            int chunk = tid + j * 256;       // 0..4095
            int t   = chunk >> 10;           // tile: Ah,Al,Bh,Bl
            int i   = chunk & 1023;
            int row = i >> 3;
            int c16 = i & 7;                 // 16B column
            cp16(base + t * TILE_B + row * RSB + c16 * 16,
                 srcs[t] + (size_t)row * Cv + k0 + c16 * 8);
        }
        asm volatile("cp.async.commit_group;" ::: "memory");
    };

    load_stage(0, 0);

    // ldmatrix lane addressing (constant offsets)
    const int ra   = lane & 15;              // A: row within 16
    const int ca   = (lane >> 4) * 8;        // A: k offset 0/8
    const int rb   = lane & 7;               // B: row within 8
    const int cb   = ((lane >> 3) & 1) * 8;  // B: k offset 0/8

    for (int c = 0; c < CHUNKS; c++) {
        const int s = c & 1;
        if (c + 1 < CHUNKS) {
            load_stage(c + 1, (c + 1) & 1);
            asm volatile("cp.async.wait_group 1;" ::: "memory");
        } else {
            asm volatile("cp.async.wait_group 0;" ::: "memory");
        }
        __syncthreads();

        const uint32_t base = sb + s * STAGE_B;
        const uint32_t aH = base + 0 * TILE_B;
        const uint32_t aL = base + 1 * TILE_B;
        const uint32_t bH = base + 2 * TILE_B;
        const uint32_t bL = base + 3 * TILE_B;

#pragma unroll
        for (int ks = 0; ks < 4; ks++) {
            const int k16 = ks * 16;
            uint32_t ah[4][4], al[4][4], bh[4][2], bl[4][2];

#pragma unroll
            for (int mi = 0; mi < 4; mi++) {
                uint32_t off = (warp_m * 64 + mi * 16 + ra) * RSB + (k16 + ca) * 2;
                asm volatile("ldmatrix.sync.aligned.m8n8.x4.shared.b16 "
                             "{%0,%1,%2,%3}, [%4];"
                             : "=r"(ah[mi][0]), "=r"(ah[mi][1]),
                               "=r"(ah[mi][2]), "=r"(ah[mi][3])
                             : "r"(aH + off));
                asm volatile("ldmatrix.sync.aligned.m8n8.x4.shared.b16 "
                             "{%0,%1,%2,%3}, [%4];"
                             : "=r"(al[mi][0]), "=r"(al[mi][1]),
                               "=r"(al[mi][2]), "=r"(al[mi][3])
                             : "r"(aL + off));
            }
#pragma unroll
            for (int ni = 0; ni < 4; ni++) {
                uint32_t off = (warp_n * 32 + ni * 8 + rb) * RSB + (k16 + cb) * 2;
                asm volatile("ldmatrix.sync.aligned.m8n8.x2.shared.b16 "
                             "{%0,%1}, [%2];"
                             : "=r"(bh[ni][0]), "=r"(bh[ni][1])
                             : "r"(bH + off));
                asm volatile("ldmatrix.sync.aligned.m8n8.x2.shared.b16 "
                             "{%0,%1}, [%2];"
                             : "=r"(bl[ni][0]), "=r"(bl[ni][1])
                             : "r"(bL + off));
            }

#pragma unroll
            for (int mi = 0; mi < 4; mi++) {
#pragma unroll
                for (int ni = 0; ni < 4; ni++) {
                    float* d = acc[mi][ni];
                    asm volatile(
                        "mma.sync.aligned.m16n8k16.row.col.f32.bf16.bf16.f32 "
                        "{%0,%1,%2,%3}, {%4,%5,%6,%7}, {%8,%9}, {%0,%1,%2,%3};"
                        : "+f"(d[0]), "+f"(d[1]), "+f"(d[2]), "+f"(d[3])
                        : "r"(ah[mi][0]), "r"(ah[mi][1]), "r"(ah[mi][2]), "r"(ah[mi][3]),
                          "r"(bh[ni][0]), "r"(bh[ni][1]));
                    asm volatile(
                        "mma.sync.aligned.m16n8k16.row.col.f32.bf16.bf16.f32 "
                        "{%0,%1,%2,%3}, {%4,%5,%6,%7}, {%8,%9}, {%0,%1,%2,%3};"
                        : "+f"(d[0]), "+f"(d[1]), "+f"(d[2]), "+f"(d[3])
                        : "r"(ah[mi][0]), "r"(ah[mi][1]), "r"(ah[mi][2]), "r"(ah[mi][3]),
                          "r"(bl[ni][0]), "r"(bl[ni][1]));
                    asm volatile(
                        "mma.sync.aligned.m16n8k16.row.col.f32.bf16.bf16.f32 "
                        "{%0,%1,%2,%3}, {%4,%5,%6,%7}, {%8,%9}, {%0,%1,%2,%3};"
                        : "+f"(d[0]), "+f"(d[1]), "+f"(d[2]), "+f"(d[3])
                        : "r"(al[mi][0]), "r"(al[mi][1]), "r"(al[mi][2]), "r"(al[mi][3]),
                          "r"(bh[ni][0]), "r"(bh[ni][1]));
                }
            }
        }
        __syncthreads();
    }

    // Epilogue: acc -> Y (+bias). d0,d1: row r=lane/4, cols 2c,2c+1; d2,d3: row r+8.
    const int er = lane >> 2;
    const int ec = (lane & 3) * 2;
#pragma unroll
    for (int mi = 0; mi < 4; mi++) {
#pragma unroll
        for (int ni = 0; ni < 4; ni++) {
            int m = m0 + warp_m * 64 + mi * 16 + er;
            int n = n0 + warp_n * 32 + ni * 8 + ec;
            float b0 = bias[n], b1 = bias[n + 1];
            float* d = acc[mi][ni];
            *(float2*)(Y + (size_t)m * Cv + n) =
                make_float2(d[0] + b0, d[1] + b1);
            *(float2*)(Y + (size_t)(m + 8) * Cv + n) =
                make_float2(d[2] + b0, d[3] + b1);
        }
    }
}

// ---------------------------------------------------------------------------
// Block-sparse attention (unchanged from passing R2 kernel).
// ---------------------------------------------------------------------------
#define SP 132
#define KP 68
#define ATTN_SMEM_FLOATS (64 * 64 + 64 * SP + 64 * KP)
#define ATTN_SMEM_BYTES  (ATTN_SMEM_FLOATS * 4)

__global__ __launch_bounds__(256) void attn_kernel(
    float* __restrict__ QO, const float* __restrict__ K,
    const float* __restrict__ V)
{
    extern __shared__ __align__(16) float sm[];
    float* Qs  = sm;
    float* Ss  = Qs + 64 * 64;
    float* KVs = Ss + 64 * SP;

    const int tid = threadIdx.x;
    const int nb = blockIdx.x, h = blockIdx.y, b = blockIdx.z;
    const int qrow0 = b * Nv + nb * BSv;
    const int col0  = h * Dv;

#pragma unroll
    for (int l = 0; l < 4; l++) {
        int lin = tid + l * 256;
        int r   = lin >> 4;
        int c   = (lin & 15) * 4;
        *(float4*)&Qs[r * 64 + c] =
            *(const float4*)(QO + (size_t)(qrow0 + r) * Cv + col0 + c);
    }

    const int tq = tid >> 4, tk = tid & 15;
    const int q0 = tq * 4;
    const float scale = 0.125f;

    for (int w = 0; w < 2; w++) {
        int kb = nb - 1 + w;
        if (kb < 0) continue;
        int krow0 = b * Nv + kb * BSv;
        __syncthreads();
#pragma unroll
        for (int l = 0; l < 4; l++) {
            int lin = tid + l * 256;
            int r   = lin >> 4;
            int c   = (lin & 15) * 4;
            float4 v = *(const float4*)(K + (size_t)(krow0 + r) * Cv + col0 + c);
            KVs[(c + 0) * KP + r] = v.x;
            KVs[(c + 1) * KP + r] = v.y;
            KVs[(c + 2) * KP + r] = v.z;
            KVs[(c + 3) * KP + r] = v.w;
        }
        __syncthreads();

        float acc[4][4] = {};
        int k0 = tk * 4;
#pragma unroll 8
        for (int dd = 0; dd < 64; dd++) {
            float4 kv = *(const float4*)&KVs[dd * KP + k0];
            float a0 = Qs[(q0 + 0) * 64 + dd];
            float a1 = Qs[(q0 + 1) * 64 + dd];
            float a2 = Qs[(q0 + 2) * 64 + dd];
            float a3 = Qs[(q0 + 3) * 64 + dd];
            acc[0][0] += a0 * kv.x; acc[0][1] += a0 * kv.y;
            acc[0][2] += a0 * kv.z; acc[0][3] += a0 * kv.w;
            acc[1][0] += a1 * kv.x; acc[1][1] += a1 * kv.y;
            acc[1][2] += a1 * kv.z; acc[1][3] += a1 * kv.w;
            acc[2][0] += a2 * kv.x; acc[2][1] += a2 * kv.y;
            acc[2][2] += a2 * kv.z; acc[2][3] += a2 * kv.w;
            acc[3][0] += a3 * kv.x; acc[3][1] += a3 * kv.y;
            acc[3][2] += a3 * kv.z; acc[3][3] += a3 * kv.w;
        }
#pragma unroll
        for (int i = 0; i < 4; i++) {
            *(float4*)&Ss[(q0 + i) * SP + w * 64 + k0] =
                make_float4(acc[i][0] * scale, acc[i][1] * scale,
                            acc[i][2] * scale, acc[i][3] * scale);
        }
    }
    __syncthreads();

    if (tid < 64) {
        int i = tid;
        int jstart = (nb > 0) ? 0 : 64;
        int jend   = 64 + i;
        float* row = &Ss[i * SP];
        for (int j = jend + 1; j < 128; j++) row[j] = 0.f;
        float m = -1e30f;
        for (int j = jstart; j <= jend; j++) m = fmaxf(m, row[j]);
        float s = 0.f;
        for (int j = jstart; j <= jend; j++) {
            float e = __expf(row[j] - m);
            row[j] = e;
            s += e;
        }
        float inv = 1.f / s;
        for (int j = jstart; j <= jend; j++) row[j] *= inv;
    }

    float oacc[4][4] = {};
    const int d0 = tk * 4;
    for (int w = 0; w < 2; w++) {
        int kb = nb - 1 + w;
        if (kb < 0) continue;
        int krow0 = b * Nv + kb * BSv;
        __syncthreads();
#pragma unroll
        for (int l = 0; l < 4; l++) {
            int lin = tid + l * 256;
            int r   = lin >> 4;
            int c   = (lin & 15) * 4;
            *(float4*)&KVs[r * KP + c] =
                *(const float4*)(V + (size_t)(krow0 + r) * Cv + col0 + c);
        }
        __syncthreads();

#pragma unroll 4
        for (int k = 0; k < 64; k++) {
            float4 vv = *(const float4*)&KVs[k * KP + d0];
            float p0 = Ss[(q0 + 0) * SP + w * 64 + k];
            float p1 = Ss[(q0 + 1) * SP + w * 64 + k];
            float p2 = Ss[(q0 + 2) * SP + w * 64 + k];
            float p3 = Ss[(q0 + 3) * SP + w * 64 + k];
            oacc[0][0] += p0 * vv.x; oacc[0][1] += p0 * vv.y;
            oacc[0][2] += p0 * vv.z; oacc[0][3] += p0 * vv.w;
            oacc[1][0] += p1 * vv.x; oacc[1][1] += p1 * vv.y;
            oacc[1][2] += p1 * vv.z; oacc[1][3] += p1 * vv.w;
            oacc[2][0] += p2 * vv.x; oacc[2][1] += p2 * vv.y;
            oacc[2][2] += p2 * vv.z; oacc[2][3] += p2 * vv.w;
            oacc[3][0] += p3 * vv.x; oacc[3][1] += p3 * vv.y;
            oacc[3][2] += p3 * vv.z; oacc[3][3] += p3 * vv.w;
        }
    }

#pragma unroll
    for (int i = 0; i < 4; i++) {
        *(float4*)(QO + (size_t)(qrow0 + q0 + i) * Cv + col0 + d0) =
            make_float4(oacc[i][0], oacc[i][1], oacc[i][2], oacc[i][3]);
    }
}

// ---------------------------------------------------------------------------
extern "C" void kernel_launch(void* const* d_in, const int* in_sizes, int n_in,
                              void* d_out, int out_size)
{
    const float* x  = (const float*)d_in[0];
    const float* Wq = (const float*)d_in[1];
    const float* bq = (const float*)d_in[2];
    const float* Wk = (const float*)d_in[3];
    const float* bk = (const float*)d_in[4];
    const float* Wv = (const float*)d_in[5];
    const float* bv = (const float*)d_in[6];
    const float* Wo = (const float*)d_in[7];
    const float* bo = (const float*)d_in[8];
    float* out = (float*)d_out;

    void *qp, *kp, *vp, *xh, *xl, *oh, *ol, *wh, *wl;
    cudaGetSymbolAddress(&qp, g_Q);
    cudaGetSymbolAddress(&kp, g_K);
    cudaGetSymbolAddress(&vp, g_V);
    cudaGetSymbolAddress(&xh, g_Xhi);
    cudaGetSymbolAddress(&xl, g_Xlo);
    cudaGetSymbolAddress(&oh, g_Ohi);
    cudaGetSymbolAddress(&ol, g_Olo);
    cudaGetSymbolAddress(&wh, g_Whi);
    cudaGetSymbolAddress(&wl, g_Wlo);
    float* Qp = (float*)qp;
    float* Kp = (float*)kp;
    float* Vp = (float*)vp;
    __nv_bfloat16* Xhi = (__nv_bfloat16*)xh;
    __nv_bfloat16* Xlo = (__nv_bfloat16*)xl;
    __nv_bfloat16* Ohi = (__nv_bfloat16*)oh;
    __nv_bfloat16* Olo = (__nv_bfloat16*)ol;
    __nv_bfloat16* Whi = (__nv_bfloat16*)wh;
    __nv_bfloat16* Wlo = (__nv_bfloat16*)wl;

    cudaFuncSetAttribute(gemm_mma, cudaFuncAttributeMaxDynamicSharedMemorySize,
                         GEMM_SMEM);
    cudaFuncSetAttribute(attn_kernel, cudaFuncAttributeMaxDynamicSharedMemorySize,
                         ATTN_SMEM_BYTES);

    const size_t WSZ = (size_t)Cv * Cv;
    const int xn4 = Mv * Cv / 4;
    const int wn4 = (int)(WSZ / 4);

    // splits
    split_kernel<<<xn4 / 256, 256>>>(x, Xhi, Xlo, xn4);
    split_kernel<<<wn4 / 256, 256>>>(Wq, Whi + 0 * WSZ, Wlo + 0 * WSZ, wn4);
    split_kernel<<<wn4 / 256, 256>>>(Wk, Whi + 1 * WSZ, Wlo + 1 * WSZ, wn4);
    split_kernel<<<wn4 / 256, 256>>>(Wv, Whi + 2 * WSZ, Wlo + 2 * WSZ, wn4);
    split_kernel<<<wn4 / 256, 256>>>(Wo, Whi + 3 * WSZ, Wlo + 3 * WSZ, wn4);

    // projections (tensor-core HMMA)
    dim3 gg(Cv / 128, Mv / 128);   // (8, 128)
    gemm_mma<<<gg, 256, GEMM_SMEM>>>(Xhi, Xlo, Whi + 0 * WSZ, Wlo + 0 * WSZ, bq, Qp);
    gemm_mma<<<gg, 256, GEMM_SMEM>>>(Xhi, Xlo, Whi + 1 * WSZ, Wlo + 1 * WSZ, bk, Kp);
    gemm_mma<<<gg, 256, GEMM_SMEM>>>(Xhi, Xlo, Whi + 2 * WSZ, Wlo + 2 * WSZ, bv, Vp);

    // attention (fp32), output written back into Qp
    dim3 ga(NBv, Hv, Bv);
    attn_kernel<<<ga, 256, ATTN_SMEM_BYTES>>>(Qp, Kp, Vp);

    // output projection
    split_kernel<<<xn4 / 256, 256>>>(Qp, Ohi, Olo, xn4);
    gemm_mma<<<gg, 256, GEMM_SMEM>>>(Ohi, Olo, Whi + 3 * WSZ, Wlo + 3 * WSZ, bo, out);
}

// round 9
// speedup vs baseline: 2.3280x; 1.0456x over previous
#include <cuda_runtime.h>
#include <cuda_bf16.h>
#include <cstdint>
#include <math.h>

// Problem constants
#define Bv   4
#define Nv   4096
#define Cv   1024
#define Hv   16
#define Dv   64
#define BSv  64
#define NBv  64
#define Mv   (Bv * Nv)   // 16384 rows

typedef __nv_bfloat16 bf16;

// ---------------------------------------------------------------------------
// Scratch (device globals; no runtime allocation allowed)
// ---------------------------------------------------------------------------
__device__ bf16 g_Xhi[(size_t)Mv * Cv];
__device__ bf16 g_Xlo[(size_t)Mv * Cv];
__device__ bf16 g_Qhi[(size_t)Mv * Cv];
__device__ bf16 g_Qlo[(size_t)Mv * Cv];
__device__ bf16 g_Khi[(size_t)Mv * Cv];
__device__ bf16 g_Klo[(size_t)Mv * Cv];
__device__ bf16 g_Vhi[(size_t)Mv * Cv];
__device__ bf16 g_Vlo[(size_t)Mv * Cv];
__device__ bf16 g_Ohi[(size_t)Mv * Cv];
__device__ bf16 g_Olo[(size_t)Mv * Cv];
__device__ bf16 g_Whi[4 * (size_t)Cv * Cv];
__device__ bf16 g_Wlo[4 * (size_t)Cv * Cv];

__device__ __forceinline__ uint32_t smem_u32(const void* p) {
    return (uint32_t)__cvta_generic_to_shared(p);
}

__device__ __forceinline__ void cp16(uint32_t saddr, const void* gaddr) {
    asm volatile("cp.async.cg.shared.global [%0], [%1], 16;"
                 :: "r"(saddr), "l"(gaddr));
}

__device__ __forceinline__ void ldx4(uint32_t* r, uint32_t addr) {
    asm volatile("ldmatrix.sync.aligned.m8n8.x4.shared.b16 {%0,%1,%2,%3}, [%4];"
                 : "=r"(r[0]), "=r"(r[1]), "=r"(r[2]), "=r"(r[3]) : "r"(addr));
}

__device__ __forceinline__ void mma16816(float* d, const uint32_t* a,
                                         uint32_t b0, uint32_t b1) {
    asm volatile("mma.sync.aligned.m16n8k16.row.col.f32.bf16.bf16.f32 "
                 "{%0,%1,%2,%3}, {%4,%5,%6,%7}, {%8,%9}, {%0,%1,%2,%3};"
                 : "+f"(d[0]), "+f"(d[1]), "+f"(d[2]), "+f"(d[3])
                 : "r"(a[0]), "r"(a[1]), "r"(a[2]), "r"(a[3]), "r"(b0), "r"(b1));
}

__device__ __forceinline__ uint32_t pack2(float a, float b) {
    __nv_bfloat162 t(__float2bfloat16(a), __float2bfloat16(b));
    return *(uint32_t*)&t;
}

// ---------------------------------------------------------------------------
// Split: fp32 -> bf16 hi + bf16 lo
// ---------------------------------------------------------------------------
__global__ __launch_bounds__(256) void split_kernel(
    const float* __restrict__ src, bf16* __restrict__ hi,
    bf16* __restrict__ lo, int n4)
{
    int i = blockIdx.x * blockDim.x + threadIdx.x;
    if (i >= n4) return;
    float4 v = *(const float4*)(src + (size_t)i * 4);
    bf16 h0 = __float2bfloat16(v.x), h1 = __float2bfloat16(v.y);
    bf16 h2 = __float2bfloat16(v.z), h3 = __float2bfloat16(v.w);
    uint2 hp, lp;
    hp.x = pack2(v.x, v.y); hp.y = pack2(v.z, v.w);
    lp.x = pack2(v.x - __bfloat162float(h0), v.y - __bfloat162float(h1));
    lp.y = pack2(v.z - __bfloat162float(h2), v.w - __bfloat162float(h3));
    *(uint2*)(hi + (size_t)i * 4) = hp;
    *(uint2*)(lo + (size_t)i * 4) = lp;
}

// ---------------------------------------------------------------------------
// HMMA GEMM, split-bf16 3-product. CTA 128x128, 8 warps each 64x32.
// MODE 0: Y = fp32 out (+bias b0p), single output.
// MODE 1: merged QKV — grid.x = 24; sel = blockIdx.x>>3 picks bias/output
//         pair (Qhi/Qlo, Khi/Klo, Vhi/Vlo); writes bf16 hi/lo.
// ---------------------------------------------------------------------------
#define CHUNKS   16
#define RSB      144
#define TILE_B   (128 * RSB)
#define STAGE_B  (4 * TILE_B)
#define GEMM_SMEM (2 * STAGE_B)

template<int MODE>
__global__ __launch_bounds__(256, 1) void gemm_mma(
    const bf16* __restrict__ Ahi, const bf16* __restrict__ Alo,
    const bf16* __restrict__ Bhi, const bf16* __restrict__ Blo,
    const float* __restrict__ b0p, const float* __restrict__ b1p,
    const float* __restrict__ b2p,
    float* __restrict__ Y,
    bf16* __restrict__ O0h, bf16* __restrict__ O0l,
    bf16* __restrict__ O1h, bf16* __restrict__ O1l,
    bf16* __restrict__ O2h, bf16* __restrict__ O2l)
{
    extern __shared__ __align__(16) char smem[];

    const int tid   = threadIdx.x;
    const int lane  = tid & 31;
    const int wid   = tid >> 5;
    const int warp_m = wid >> 2;
    const int warp_n = wid & 3;
    const int n0 = blockIdx.x * 128;       // global col into concat B
    const int m0 = blockIdx.y * 128;

    const bf16* srcs[4] = {
        Ahi + (size_t)m0 * Cv, Alo + (size_t)m0 * Cv,
        Bhi + (size_t)n0 * Cv, Blo + (size_t)n0 * Cv };

    const uint32_t sb = smem_u32(smem);

    float acc[4][4][4];
#pragma unroll
    for (int mi = 0; mi < 4; mi++)
#pragma unroll
        for (int ni = 0; ni < 4; ni++)
#pragma unroll
            for (int f = 0; f < 4; f++) acc[mi][ni][f] = 0.f;

    auto load_stage = [&](int c, int s) {
        const int k0 = c * 64;
        const uint32_t base = sb + s * STAGE_B;
#pragma unroll
        for (int j = 0; j < 16; j++) {
            int chunk = tid + j * 256;
            int t   = chunk >> 10;
            int i   = chunk & 1023;
            int row = i >> 3;
            int c16 = i & 7;
            cp16(base + t * TILE_B + row * RSB + c16 * 16,
                 srcs[t] + (size_t)row * Cv + k0 + c16 * 8);
        }
        asm volatile("cp.async.commit_group;" ::: "memory");
    };

    load_stage(0, 0);

    const int ra = lane & 15;
    const int ca = (lane >> 4) * 8;
    const int rb = lane & 7;
    const int cb = ((lane >> 3) & 1) * 8;

    for (int c = 0; c < CHUNKS; c++) {
        const int s = c & 1;
        if (c + 1 < CHUNKS) {
            load_stage(c + 1, (c + 1) & 1);
            asm volatile("cp.async.wait_group 1;" ::: "memory");
        } else {
            asm volatile("cp.async.wait_group 0;" ::: "memory");
        }
        __syncthreads();

        const uint32_t base = sb + s * STAGE_B;
        const uint32_t aH = base + 0 * TILE_B;
        const uint32_t aL = base + 1 * TILE_B;
        const uint32_t bH = base + 2 * TILE_B;
        const uint32_t bL = base + 3 * TILE_B;

#pragma unroll
        for (int ks = 0; ks < 4; ks++) {
            const int k16 = ks * 16;
            uint32_t ah[4][4], al[4][4], bh[4][2], bl[4][2];
#pragma unroll
            for (int mi = 0; mi < 4; mi++) {
                uint32_t off = (warp_m * 64 + mi * 16 + ra) * RSB + (k16 + ca) * 2;
                ldx4(ah[mi], aH + off);
                ldx4(al[mi], aL + off);
            }
#pragma unroll
            for (int ni = 0; ni < 4; ni++) {
                uint32_t off = (warp_n * 32 + ni * 8 + rb) * RSB + (k16 + cb) * 2;
                asm volatile("ldmatrix.sync.aligned.m8n8.x2.shared.b16 {%0,%1}, [%2];"
                             : "=r"(bh[ni][0]), "=r"(bh[ni][1]) : "r"(bH + off));
                asm volatile("ldmatrix.sync.aligned.m8n8.x2.shared.b16 {%0,%1}, [%2];"
                             : "=r"(bl[ni][0]), "=r"(bl[ni][1]) : "r"(bL + off));
            }
#pragma unroll
            for (int mi = 0; mi < 4; mi++)
#pragma unroll
                for (int ni = 0; ni < 4; ni++) {
                    mma16816(acc[mi][ni], ah[mi], bh[ni][0], bh[ni][1]);
                    mma16816(acc[mi][ni], ah[mi], bl[ni][0], bl[ni][1]);
                    mma16816(acc[mi][ni], al[mi], bh[ni][0], bh[ni][1]);
                }
        }
        __syncthreads();
    }

    const int er = lane >> 2;
    const int ec = (lane & 3) * 2;

    if (MODE == 0) {
#pragma unroll
        for (int mi = 0; mi < 4; mi++)
#pragma unroll
            for (int ni = 0; ni < 4; ni++) {
                int m = m0 + warp_m * 64 + mi * 16 + er;
                int n = n0 + warp_n * 32 + ni * 8 + ec;
                float bb0 = b0p[n], bb1 = b0p[n + 1];
                float* d = acc[mi][ni];
                *(float2*)(Y + (size_t)m * Cv + n) = make_float2(d[0] + bb0, d[1] + bb1);
                *(float2*)(Y + (size_t)(m + 8) * Cv + n) = make_float2(d[2] + bb0, d[3] + bb1);
            }
    } else {
        const int sel = blockIdx.x >> 3;
        const int nl0 = (blockIdx.x & 7) * 128;
        const float* bias = (sel == 0) ? b0p : (sel == 1) ? b1p : b2p;
        bf16* Yh = (sel == 0) ? O0h : (sel == 1) ? O1h : O2h;
        bf16* Yl = (sel == 0) ? O0l : (sel == 1) ? O1l : O2l;
#pragma unroll
        for (int mi = 0; mi < 4; mi++)
#pragma unroll
            for (int ni = 0; ni < 4; ni++) {
                int m = m0 + warp_m * 64 + mi * 16 + er;
                int n = nl0 + warp_n * 32 + ni * 8 + ec;
                float bb0 = bias[n], bb1 = bias[n + 1];
                float* d = acc[mi][ni];
#pragma unroll
                for (int rr = 0; rr < 2; rr++) {
                    int mm = m + rr * 8;
                    float v0 = d[rr * 2 + 0] + bb0;
                    float v1 = d[rr * 2 + 1] + bb1;
                    bf16 h0 = __float2bfloat16(v0);
                    bf16 h1 = __float2bfloat16(v1);
                    __nv_bfloat162 hp(h0, h1);
                    *(uint32_t*)(Yh + (size_t)mm * Cv + n) = *(uint32_t*)&hp;
                    *(uint32_t*)(Yl + (size_t)mm * Cv + n) =
                        pack2(v0 - __bfloat162float(h0), v1 - __bfloat162float(h1));
                }
            }
    }
}

// ---------------------------------------------------------------------------
// Tensor-core block-sparse attention. One CTA per (query block, head, batch).
// Window = [prev (clamped), self]; next block fully causal-masked.
// Q,K as bf16 hi/lo; scores split-bf16 3-product; register softmax;
// P split in-register; P@V split-bf16 3-product with V transposed in smem.
// ---------------------------------------------------------------------------
#define ARS 144                  // Q/K smem row stride bytes (64 bf16 + pad)
#define PRS 272                  // P/Vt smem row stride bytes (128 bf16 + pad)
#define OFF_QH   0
#define OFF_QL   9216
#define OFF_KH   18432
#define OFF_KL   36864
#define OFF_VTH  55296
#define OFF_VTL  72704
#define OFF_PH   90112
#define OFF_PL   107520
#define OFF_RMAX 124928
#define OFF_RSUM 125440
#define ATTN_SMEM 125952

__global__ __launch_bounds__(256, 1) void attn_tc(
    const bf16* __restrict__ Qhi, const bf16* __restrict__ Qlo,
    const bf16* __restrict__ Khi, const bf16* __restrict__ Klo,
    const bf16* __restrict__ Vhi, const bf16* __restrict__ Vlo,
    bf16* __restrict__ Ohi, bf16* __restrict__ Olo)
{
    extern __shared__ __align__(16) char sm[];
    const int tid  = threadIdx.x;
    const int lane = tid & 31;
    const int wid  = tid >> 5;
    const int warp_m = wid >> 1;          // 0..3 : 16 q-rows each
    const int warp_n = wid & 1;           // 0..1
    const int nb = blockIdx.x, h = blockIdx.y, b = blockIdx.z;
    const int qrow0 = b * Nv + nb * BSv;
    const int col0  = h * Dv;
    const int kb0 = (nb > 0) ? nb - 1 : 0;   // clamped (masked when nb==0)

    const uint32_t sb = smem_u32(sm);

    // ---- loads: Q, K via cp.async; V transposed via scalar stores ----
#pragma unroll
    for (int it = 0; it < 4; it++) {
        int lin = it * 256 + tid;            // 0..1023
        int t = lin >> 9, i = lin & 511;
        int r = i >> 3, c = i & 7;
        const bf16* src = (t ? Qlo : Qhi) + (size_t)(qrow0 + r) * Cv + col0 + c * 8;
        cp16(sb + (t ? OFF_QL : OFF_QH) + r * ARS + c * 16, src);
    }
#pragma unroll
    for (int it = 0; it < 8; it++) {
        int lin = it * 256 + tid;            // 0..2047
        int t = lin >> 10, i = lin & 1023;
        int r = i >> 3, c = i & 7;
        int krow = b * Nv + (r < 64 ? kb0 * 64 + r : nb * 64 + (r - 64));
        const bf16* src = (t ? Klo : Khi) + (size_t)krow * Cv + col0 + c * 8;
        cp16(sb + (t ? OFF_KL : OFF_KH) + r * ARS + c * 16, src);
    }
    asm volatile("cp.async.commit_group;" ::: "memory");

#pragma unroll
    for (int t = 0; t < 2; t++) {
        const bf16* Vsrc = t ? Vlo : Vhi;
        char* vt = sm + (t ? OFF_VTL : OFF_VTH);
#pragma unroll
        for (int it = 0; it < 16; it++) {
            int lin = it * 256 + tid;        // 0..4095
            int key = lin >> 5, dp = lin & 31;
            int krow = b * Nv + (key < 64 ? kb0 * 64 + key : nb * 64 + (key - 64));
            uint32_t v = *(const uint32_t*)(Vsrc + (size_t)krow * Cv + col0 + dp * 2);
            *(uint16_t*)(vt + (2 * dp + 0) * PRS + key * 2) = (uint16_t)(v & 0xffff);
            *(uint16_t*)(vt + (2 * dp + 1) * PRS + key * 2) = (uint16_t)(v >> 16);
        }
    }
    asm volatile("cp.async.wait_group 0;" ::: "memory");
    __syncthreads();

    // ---- QK^T : per warp 16 q-rows x 64 key-cols (8 n8 tiles) ----
    const int ra = lane & 15;
    const int ca = (lane >> 4) * 8;
    float acc[8][4];
#pragma unroll
    for (int ni = 0; ni < 8; ni++)
#pragma unroll
        for (int f = 0; f < 4; f++) acc[ni][f] = 0.f;

#pragma unroll
    for (int ks = 0; ks < 4; ks++) {
        uint32_t ah[4], al[4];
        uint32_t aoff = (warp_m * 16 + ra) * ARS + (ks * 16 + ca) * 2;
        ldx4(ah, sb + OFF_QH + aoff);
        ldx4(al, sb + OFF_QL + aoff);
        uint32_t bh[4][4], bl[4][4];
#pragma unroll
        for (int pb = 0; pb < 4; pb++) {
            uint32_t boff = (warp_n * 64 + pb * 16 + ra) * ARS + (ks * 16 + ca) * 2;
            ldx4(bh[pb], sb + OFF_KH + boff);
            ldx4(bl[pb], sb + OFF_KL + boff);
        }
#pragma unroll
        for (int pb = 0; pb < 4; pb++)
#pragma unroll
            for (int hf = 0; hf < 2; hf++) {
                int ni = pb * 2 + hf;
                mma16816(acc[ni], ah, bh[pb][hf], bh[pb][hf + 2]);
                mma16816(acc[ni], ah, bl[pb][hf], bl[pb][hf + 2]);
                mma16816(acc[ni], al, bh[pb][hf], bh[pb][hf + 2]);
            }
    }

    // ---- mask + softmax (register, shfl + cross-warp smem reduce) ----
    const int er = lane >> 2;
    const int ec = (lane & 3) * 2;
    const int iq = warp_m * 16 + er;        // q row (also +8)
    const float scale = 0.125f;

#pragma unroll
    for (int ni = 0; ni < 8; ni++)
#pragma unroll
        for (int f = 0; f < 4; f++) {
            int i = iq + ((f >= 2) ? 8 : 0);
            int j = warp_n * 64 + ni * 8 + ec + (f & 1);
            bool valid = (64 + i >= j) && (nb > 0 || j >= 64);
            acc[ni][f] = valid ? acc[ni][f] * scale : -1e30f;
        }

    float m0 = -1e30f, m1 = -1e30f;
#pragma unroll
    for (int ni = 0; ni < 8; ni++) {
        m0 = fmaxf(m0, fmaxf(acc[ni][0], acc[ni][1]));
        m1 = fmaxf(m1, fmaxf(acc[ni][2], acc[ni][3]));
    }
    m0 = fmaxf(m0, __shfl_xor_sync(0xffffffffu, m0, 1));
    m0 = fmaxf(m0, __shfl_xor_sync(0xffffffffu, m0, 2));
    m1 = fmaxf(m1, __shfl_xor_sync(0xffffffffu, m1, 1));
    m1 = fmaxf(m1, __shfl_xor_sync(0xffffffffu, m1, 2));
    float* rmax = (float*)(sm + OFF_RMAX);
    if ((lane & 3) == 0) {
        rmax[iq * 2 + warp_n] = m0;
        rmax[(iq + 8) * 2 + warp_n] = m1;
    }
    __syncthreads();
    float g0 = fmaxf(rmax[iq * 2], rmax[iq * 2 + 1]);
    float g1 = fmaxf(rmax[(iq + 8) * 2], rmax[(iq + 8) * 2 + 1]);

    float s0 = 0.f, s1 = 0.f;
#pragma unroll
    for (int ni = 0; ni < 8; ni++) {
        acc[ni][0] = __expf(acc[ni][0] - g0);
        acc[ni][1] = __expf(acc[ni][1] - g0);
        acc[ni][2] = __expf(acc[ni][2] - g1);
        acc[ni][3] = __expf(acc[ni][3] - g1);
        s0 += acc[ni][0] + acc[ni][1];
        s1 += acc[ni][2] + acc[ni][3];
    }
    s0 += __shfl_xor_sync(0xffffffffu, s0, 1);
    s0 += __shfl_xor_sync(0xffffffffu, s0, 2);
    s1 += __shfl_xor_sync(0xffffffffu, s1, 1);
    s1 += __shfl_xor_sync(0xffffffffu, s1, 2);
    float* rsum = (float*)(sm + OFF_RSUM);
    if ((lane & 3) == 0) {
        rsum[iq * 2 + warp_n] = s0;
        rsum[(iq + 8) * 2 + warp_n] = s1;
    }
    __syncthreads();
    float inv0 = 1.f / (rsum[iq * 2] + rsum[iq * 2 + 1]);
    float inv1 = 1.f / (rsum[(iq + 8) * 2] + rsum[(iq + 8) * 2 + 1]);

    // write P hi/lo (bf16) to smem
#pragma unroll
    for (int ni = 0; ni < 8; ni++) {
        float p0 = acc[ni][0] * inv0, p1 = acc[ni][1] * inv0;
        float p2 = acc[ni][2] * inv1, p3 = acc[ni][3] * inv1;
        int j = warp_n * 64 + ni * 8 + ec;
        bf16 h0 = __float2bfloat16(p0), h1 = __float2bfloat16(p1);
        bf16 h2 = __float2bfloat16(p2), h3 = __float2bfloat16(p3);
        __nv_bfloat162 hA(h0, h1), hB(h2, h3);
        *(uint32_t*)(sm + OFF_PH + iq * PRS + j * 2) = *(uint32_t*)&hA;
        *(uint32_t*)(sm + OFF_PH + (iq + 8) * PRS + j * 2) = *(uint32_t*)&hB;
        *(uint32_t*)(sm + OFF_PL + iq * PRS + j * 2) =
            pack2(p0 - __bfloat162float(h0), p1 - __bfloat162float(h1));
        *(uint32_t*)(sm + OFF_PL + (iq + 8) * PRS + j * 2) =
            pack2(p2 - __bfloat162float(h2), p3 - __bfloat162float(h3));
    }
    __syncthreads();

    // ---- P @ V : per warp 16 q-rows x 32 d-cols (4 n8 tiles), k=128 keys ----
    float oacc[4][4];
#pragma unroll
    for (int ni = 0; ni < 4; ni++)
#pragma unroll
        for (int f = 0; f < 4; f++) oacc[ni][f] = 0.f;

#pragma unroll
    for (int ks = 0; ks < 8; ks++) {
        uint32_t ph[4], pl[4];
        uint32_t aoff = (warp_m * 16 + ra) * PRS + (ks * 16 + ca) * 2;
        ldx4(ph, sb + OFF_PH + aoff);
        ldx4(pl, sb + OFF_PL + aoff);
        uint32_t vh[2][4], vl[2][4];
#pragma unroll
        for (int pb = 0; pb < 2; pb++) {
            uint32_t boff = (warp_n * 32 + pb * 16 + ra) * PRS + (ks * 16 + ca) * 2;
            ldx4(vh[pb], sb + OFF_VTH + boff);
            ldx4(vl[pb], sb + OFF_VTL + boff);
        }
#pragma unroll
        for (int pb = 0; pb < 2; pb++)
#pragma unroll
            for (int hf = 0; hf < 2; hf++) {
                int ni = pb * 2 + hf;
                mma16816(oacc[ni], ph, vh[pb][hf], vh[pb][hf + 2]);
                mma16816(oacc[ni], ph, vl[pb][hf], vl[pb][hf + 2]);
                mma16816(oacc[ni], pl, vh[pb][hf], vh[pb][hf + 2]);
            }
    }

    // ---- epilogue: O -> global bf16 hi/lo ----
#pragma unroll
    for (int ni = 0; ni < 4; ni++) {
        int colg = col0 + warp_n * 32 + ni * 8 + ec;
        float* d = oacc[ni];
#pragma unroll
        for (int rr = 0; rr < 2; rr++) {
            int row = qrow0 + warp_m * 16 + er + rr * 8;
            float v0 = d[rr * 2 + 0], v1 = d[rr * 2 + 1];
            bf16 h0 = __float2bfloat16(v0), h1 = __float2bfloat16(v1);
            __nv_bfloat162 hp(h0, h1);
            *(uint32_t*)(Ohi + (size_t)row * Cv + colg) = *(uint32_t*)&hp;
            *(uint32_t*)(Olo + (size_t)row * Cv + colg) =
                pack2(v0 - __bfloat162float(h0), v1 - __bfloat162float(h1));
        }
    }
}

// ---------------------------------------------------------------------------
extern "C" void kernel_launch(void* const* d_in, const int* in_sizes, int n_in,
                              void* d_out, int out_size)
{
    const float* x  = (const float*)d_in[0];
    const float* Wq = (const float*)d_in[1];
    const float* bq = (const float*)d_in[2];
    const float* Wk = (const float*)d_in[3];
    const float* bk = (const float*)d_in[4];
    const float* Wv = (const float*)d_in[5];
    const float* bv = (const float*)d_in[6];
    const float* Wo = (const float*)d_in[7];
    const float* bo = (const float*)d_in[8];
    float* out = (float*)d_out;

    void *p;
    bf16 *Xhi, *Xlo, *Qh, *Ql, *Kh, *Kl, *Vh, *Vl, *Oh, *Ol, *Whi, *Wlo;
    cudaGetSymbolAddress(&p, g_Xhi); Xhi = (bf16*)p;
    cudaGetSymbolAddress(&p, g_Xlo); Xlo = (bf16*)p;
    cudaGetSymbolAddress(&p, g_Qhi); Qh = (bf16*)p;
    cudaGetSymbolAddress(&p, g_Qlo); Ql = (bf16*)p;
    cudaGetSymbolAddress(&p, g_Khi); Kh = (bf16*)p;
    cudaGetSymbolAddress(&p, g_Klo); Kl = (bf16*)p;
    cudaGetSymbolAddress(&p, g_Vhi); Vh = (bf16*)p;
    cudaGetSymbolAddress(&p, g_Vlo); Vl = (bf16*)p;
    cudaGetSymbolAddress(&p, g_Ohi); Oh = (bf16*)p;
    cudaGetSymbolAddress(&p, g_Olo); Ol = (bf16*)p;
    cudaGetSymbolAddress(&p, g_Whi); Whi = (bf16*)p;
    cudaGetSymbolAddress(&p, g_Wlo); Wlo = (bf16*)p;

    cudaFuncSetAttribute(gemm_mma<0>, cudaFuncAttributeMaxDynamicSharedMemorySize, GEMM_SMEM);
    cudaFuncSetAttribute(gemm_mma<1>, cudaFuncAttributeMaxDynamicSharedMemorySize, GEMM_SMEM);
    cudaFuncSetAttribute(attn_tc, cudaFuncAttributeMaxDynamicSharedMemorySize, ATTN_SMEM);

    const size_t WSZ = (size_t)Cv * Cv;
    const int xn4 = Mv * Cv / 4;
    const int wn4 = (int)(WSZ / 4);

    split_kernel<<<xn4 / 256, 256>>>(x, Xhi, Xlo, xn4);
    split_kernel<<<wn4 / 256, 256>>>(Wq, Whi + 0 * WSZ, Wlo + 0 * WSZ, wn4);
    split_kernel<<<wn4 / 256, 256>>>(Wk, Whi + 1 * WSZ, Wlo + 1 * WSZ, wn4);
    split_kernel<<<wn4 / 256, 256>>>(Wv, Whi + 2 * WSZ, Wlo + 2 * WSZ, wn4);
    split_kernel<<<wn4 / 256, 256>>>(Wo, Whi + 3 * WSZ, Wlo + 3 * WSZ, wn4);

    // merged QKV projection (tensor-core), bf16 hi/lo outputs
    dim3 gq(24, Mv / 128);
    gemm_mma<1><<<gq, 256, GEMM_SMEM>>>(Xhi, Xlo, Whi, Wlo, bq, bk, bv,
                                        nullptr, Qh, Ql, Kh, Kl, Vh, Vl);

    // tensor-core attention -> Ohi/Olo
    dim3 ga(NBv, Hv, Bv);
    attn_tc<<<ga, 256, ATTN_SMEM>>>(Qh, Ql, Kh, Kl, Vh, Vl, Oh, Ol);

    // output projection (fp32 out)
    dim3 gg(Cv / 128, Mv / 128);
    gemm_mma<0><<<gg, 256, GEMM_SMEM>>>(Oh, Ol, Whi + 3 * WSZ, Wlo + 3 * WSZ,
                                        bo, nullptr, nullptr, out,
                                        nullptr, nullptr, nullptr, nullptr,
                                        nullptr, nullptr);
}

// round 10
// speedup vs baseline: 3.2031x; 1.3759x over previous
#include <cuda_runtime.h>
#include <cuda_fp16.h>
#include <cstdint>
#include <math.h>

// Problem constants
#define Bv   4
#define Nv   4096
#define Cv   1024
#define Hv   16
#define Dv   64
#define BSv  64
#define NBv  64
#define Mv   (Bv * Nv)   // 16384 rows

typedef __half h16;

// ---------------------------------------------------------------------------
// Scratch (device globals; no runtime allocation allowed)
// ---------------------------------------------------------------------------
__device__ h16 g_Xh[(size_t)Mv * Cv];
__device__ h16 g_Qh[(size_t)Mv * Cv];
__device__ h16 g_Ql[(size_t)Mv * Cv];
__device__ h16 g_Kh[(size_t)Mv * Cv];
__device__ h16 g_Kl[(size_t)Mv * Cv];
__device__ h16 g_Vh[(size_t)Mv * Cv];
__device__ h16 g_Vl[(size_t)Mv * Cv];
__device__ h16 g_Oh[(size_t)Mv * Cv];
__device__ h16 g_Wh[4 * (size_t)Cv * Cv];
__device__ h16 g_Wl[4 * (size_t)Cv * Cv];

__device__ __forceinline__ uint32_t smem_u32(const void* p) {
    return (uint32_t)__cvta_generic_to_shared(p);
}

__device__ __forceinline__ void cp16(uint32_t saddr, const void* gaddr) {
    asm volatile("cp.async.cg.shared.global [%0], [%1], 16;"
                 :: "r"(saddr), "l"(gaddr));
}

__device__ __forceinline__ void ldx4(uint32_t* r, uint32_t addr) {
    asm volatile("ldmatrix.sync.aligned.m8n8.x4.shared.b16 {%0,%1,%2,%3}, [%4];"
                 : "=r"(r[0]), "=r"(r[1]), "=r"(r[2]), "=r"(r[3]) : "r"(addr));
}

__device__ __forceinline__ void mma16816(float* d, const uint32_t* a,
                                         uint32_t b0, uint32_t b1) {
    asm volatile("mma.sync.aligned.m16n8k16.row.col.f32.f16.f16.f32 "
                 "{%0,%1,%2,%3}, {%4,%5,%6,%7}, {%8,%9}, {%0,%1,%2,%3};"
                 : "+f"(d[0]), "+f"(d[1]), "+f"(d[2]), "+f"(d[3])
                 : "r"(a[0]), "r"(a[1]), "r"(a[2]), "r"(a[3]), "r"(b0), "r"(b1));
}

__device__ __forceinline__ uint32_t pack2h(float a, float b) {
    __half2 t(__float2half_rn(a), __float2half_rn(b));
    return *(uint32_t*)&t;
}

// ---------------------------------------------------------------------------
// Splits: fp32 -> fp16 hi (+ optional fp16 lo = rn(x - float(hi)))
// ---------------------------------------------------------------------------
__global__ __launch_bounds__(256) void split_hi(
    const float* __restrict__ src, h16* __restrict__ hi, int n4)
{
    int i = blockIdx.x * blockDim.x + threadIdx.x;
    if (i >= n4) return;
    float4 v = *(const float4*)(src + (size_t)i * 4);
    uint2 hp;
    hp.x = pack2h(v.x, v.y); hp.y = pack2h(v.z, v.w);
    *(uint2*)(hi + (size_t)i * 4) = hp;
}

__global__ __launch_bounds__(256) void split_hilo(
    const float* __restrict__ src, h16* __restrict__ hi,
    h16* __restrict__ lo, int n4)
{
    int i = blockIdx.x * blockDim.x + threadIdx.x;
    if (i >= n4) return;
    float4 v = *(const float4*)(src + (size_t)i * 4);
    h16 h0 = __float2half_rn(v.x), h1 = __float2half_rn(v.y);
    h16 h2 = __float2half_rn(v.z), h3 = __float2half_rn(v.w);
    uint2 hp, lp;
    __half2 t01(h0, h1), t23(h2, h3);
    hp.x = *(uint32_t*)&t01; hp.y = *(uint32_t*)&t23;
    lp.x = pack2h(v.x - __half2float(h0), v.y - __half2float(h1));
    lp.y = pack2h(v.z - __half2float(h2), v.w - __half2float(h3));
    *(uint2*)(hi + (size_t)i * 4) = hp;
    *(uint2*)(lo + (size_t)i * 4) = lp;
}

// ---------------------------------------------------------------------------
// HMMA GEMM, 2-product fp16: Y ~= Ahi*(Bhi + Blo). CTA 128x128, 8 warps 64x32.
// MODE 0: fp32 out (+bias b0p).
// MODE 1: merged QKV — grid.x=24; sel=blockIdx.x>>3 -> (Qh/Ql, Kh/Kl, Vh/Vl),
//         writes fp16 hi/lo.
// ---------------------------------------------------------------------------
#define CHUNKS   16
#define RSB      144
#define TILE_B   (128 * RSB)               // 18432
#define STAGE_B  (3 * TILE_B)              // 55296
#define GEMM_SMEM (2 * STAGE_B)            // 110592

template<int MODE>
__global__ __launch_bounds__(256, 1) void gemm_mma(
    const h16* __restrict__ Ah,
    const h16* __restrict__ Bh, const h16* __restrict__ Bl,
    const float* __restrict__ b0p, const float* __restrict__ b1p,
    const float* __restrict__ b2p,
    float* __restrict__ Y,
    h16* __restrict__ O0h, h16* __restrict__ O0l,
    h16* __restrict__ O1h, h16* __restrict__ O1l,
    h16* __restrict__ O2h, h16* __restrict__ O2l)
{
    extern __shared__ __align__(16) char smem[];

    const int tid   = threadIdx.x;
    const int lane  = tid & 31;
    const int wid   = tid >> 5;
    const int warp_m = wid >> 2;
    const int warp_n = wid & 3;
    const int n0 = blockIdx.x * 128;       // col into (possibly concat) B
    const int m0 = blockIdx.y * 128;

    const h16* srcs[3] = {
        Ah + (size_t)m0 * Cv, Bh + (size_t)n0 * Cv, Bl + (size_t)n0 * Cv };

    const uint32_t sb = smem_u32(smem);

    float acc[4][4][4];
#pragma unroll
    for (int mi = 0; mi < 4; mi++)
#pragma unroll
        for (int ni = 0; ni < 4; ni++)
#pragma unroll
            for (int f = 0; f < 4; f++) acc[mi][ni][f] = 0.f;

    auto load_stage = [&](int c, int s) {
        const int k0 = c * 64;
        const uint32_t base = sb + s * STAGE_B;
#pragma unroll
        for (int j = 0; j < 12; j++) {
            int chunk = tid + j * 256;       // 0..3071
            int t   = chunk >> 10;           // 0..2 : Ah, Bh, Bl
            int i   = chunk & 1023;
            int row = i >> 3;
            int c16 = i & 7;
            cp16(base + t * TILE_B + row * RSB + c16 * 16,
                 srcs[t] + (size_t)row * Cv + k0 + c16 * 8);
        }
        asm volatile("cp.async.commit_group;" ::: "memory");
    };

    load_stage(0, 0);

    const int ra = lane & 15;
    const int ca = (lane >> 4) * 8;
    const int rb = lane & 7;
    const int cb = ((lane >> 3) & 1) * 8;

    for (int c = 0; c < CHUNKS; c++) {
        const int s = c & 1;
        if (c + 1 < CHUNKS) {
            load_stage(c + 1, (c + 1) & 1);
            asm volatile("cp.async.wait_group 1;" ::: "memory");
        } else {
            asm volatile("cp.async.wait_group 0;" ::: "memory");
        }
        __syncthreads();

        const uint32_t base = sb + s * STAGE_B;
        const uint32_t aH = base + 0 * TILE_B;
        const uint32_t bH = base + 1 * TILE_B;
        const uint32_t bL = base + 2 * TILE_B;

#pragma unroll
        for (int ks = 0; ks < 4; ks++) {
            const int k16 = ks * 16;
            uint32_t ah[4][4], bh[4][2], bl[4][2];
#pragma unroll
            for (int mi = 0; mi < 4; mi++) {
                uint32_t off = (warp_m * 64 + mi * 16 + ra) * RSB + (k16 + ca) * 2;
                ldx4(ah[mi], aH + off);
            }
#pragma unroll
            for (int ni = 0; ni < 4; ni++) {
                uint32_t off = (warp_n * 32 + ni * 8 + rb) * RSB + (k16 + cb) * 2;
                asm volatile("ldmatrix.sync.aligned.m8n8.x2.shared.b16 {%0,%1}, [%2];"
                             : "=r"(bh[ni][0]), "=r"(bh[ni][1]) : "r"(bH + off));
                asm volatile("ldmatrix.sync.aligned.m8n8.x2.shared.b16 {%0,%1}, [%2];"
                             : "=r"(bl[ni][0]), "=r"(bl[ni][1]) : "r"(bL + off));
            }
#pragma unroll
            for (int mi = 0; mi < 4; mi++)
#pragma unroll
                for (int ni = 0; ni < 4; ni++) {
                    mma16816(acc[mi][ni], ah[mi], bh[ni][0], bh[ni][1]);
                    mma16816(acc[mi][ni], ah[mi], bl[ni][0], bl[ni][1]);
                }
        }
        __syncthreads();
    }

    const int er = lane >> 2;
    const int ec = (lane & 3) * 2;

    if (MODE == 0) {
#pragma unroll
        for (int mi = 0; mi < 4; mi++)
#pragma unroll
            for (int ni = 0; ni < 4; ni++) {
                int m = m0 + warp_m * 64 + mi * 16 + er;
                int n = n0 + warp_n * 32 + ni * 8 + ec;
                float bb0 = b0p[n], bb1 = b0p[n + 1];
                float* d = acc[mi][ni];
                *(float2*)(Y + (size_t)m * Cv + n) = make_float2(d[0] + bb0, d[1] + bb1);
                *(float2*)(Y + (size_t)(m + 8) * Cv + n) = make_float2(d[2] + bb0, d[3] + bb1);
            }
    } else {
        const int sel = blockIdx.x >> 3;
        const int nl0 = (blockIdx.x & 7) * 128;
        const float* bias = (sel == 0) ? b0p : (sel == 1) ? b1p : b2p;
        h16* Yh = (sel == 0) ? O0h : (sel == 1) ? O1h : O2h;
        h16* Yl = (sel == 0) ? O0l : (sel == 1) ? O1l : O2l;
#pragma unroll
        for (int mi = 0; mi < 4; mi++)
#pragma unroll
            for (int ni = 0; ni < 4; ni++) {
                int m = m0 + warp_m * 64 + mi * 16 + er;
                int n = nl0 + warp_n * 32 + ni * 8 + ec;
                float bb0 = bias[n], bb1 = bias[n + 1];
                float* d = acc[mi][ni];
#pragma unroll
                for (int rr = 0; rr < 2; rr++) {
                    int mm = m + rr * 8;
                    float v0 = d[rr * 2 + 0] + bb0;
                    float v1 = d[rr * 2 + 1] + bb1;
                    h16 h0 = __float2half_rn(v0);
                    h16 h1 = __float2half_rn(v1);
                    __half2 hp(h0, h1);
                    *(uint32_t*)(Yh + (size_t)mm * Cv + n) = *(uint32_t*)&hp;
                    if (Yl)
                        *(uint32_t*)(Yl + (size_t)mm * Cv + n) =
                            pack2h(v0 - __half2float(h0), v1 - __half2float(h1));
                }
            }
    }
}

// ---------------------------------------------------------------------------
// Tensor-core block-sparse attention, 2-product fp16.
// S ~= Qhi*(Khi+Klo); O ~= Phi*(Vhi+Vlo). One CTA per (q-block, head, batch).
// ---------------------------------------------------------------------------
#define ARS 144                  // Q/K smem row stride bytes
#define PRS 272                  // P/Vt smem row stride bytes
#define OFF_QH   0
#define OFF_KH   9216
#define OFF_KL   27648
#define OFF_VTH  46080
#define OFF_VTL  63488
#define OFF_PH   80896
#define OFF_RMAX 98304
#define OFF_RSUM 98816
#define ATTN_SMEM 99328

__global__ __launch_bounds__(256, 1) void attn_tc(
    const h16* __restrict__ Qh,
    const h16* __restrict__ Kh, const h16* __restrict__ Kl,
    const h16* __restrict__ Vh, const h16* __restrict__ Vl,
    h16* __restrict__ Oh)
{
    extern __shared__ __align__(16) char sm[];
    const int tid  = threadIdx.x;
    const int lane = tid & 31;
    const int wid  = tid >> 5;
    const int warp_m = wid >> 1;          // 0..3 : 16 q-rows
    const int warp_n = wid & 1;           // 0..1
    const int nb = blockIdx.x, h = blockIdx.y, b = blockIdx.z;
    const int qrow0 = b * Nv + nb * BSv;
    const int col0  = h * Dv;
    const int kb0 = (nb > 0) ? nb - 1 : 0;   // clamped (masked when nb==0)

    const uint32_t sb = smem_u32(sm);

    // ---- loads ----
#pragma unroll
    for (int it = 0; it < 2; it++) {
        int i = it * 256 + tid;              // 0..511
        int r = i >> 3, c = i & 7;
        cp16(sb + OFF_QH + r * ARS + c * 16,
             Qh + (size_t)(qrow0 + r) * Cv + col0 + c * 8);
    }
#pragma unroll
    for (int it = 0; it < 8; it++) {
        int lin = it * 256 + tid;            // 0..2047
        int t = lin >> 10, i = lin & 1023;
        int r = i >> 3, c = i & 7;
        int krow = b * Nv + (r < 64 ? kb0 * 64 + r : nb * 64 + (r - 64));
        const h16* src = (t ? Kl : Kh) + (size_t)krow * Cv + col0 + c * 8;
        cp16(sb + (t ? OFF_KL : OFF_KH) + r * ARS + c * 16, src);
    }
    asm volatile("cp.async.commit_group;" ::: "memory");

#pragma unroll
    for (int t = 0; t < 2; t++) {
        const h16* Vsrc = t ? Vl : Vh;
        char* vt = sm + (t ? OFF_VTL : OFF_VTH);
#pragma unroll
        for (int it = 0; it < 16; it++) {
            int lin = it * 256 + tid;        // 0..4095
            int key = lin >> 5, dp = lin & 31;
            int krow = b * Nv + (key < 64 ? kb0 * 64 + key : nb * 64 + (key - 64));
            uint32_t v = *(const uint32_t*)(Vsrc + (size_t)krow * Cv + col0 + dp * 2);
            *(uint16_t*)(vt + (2 * dp + 0) * PRS + key * 2) = (uint16_t)(v & 0xffff);
            *(uint16_t*)(vt + (2 * dp + 1) * PRS + key * 2) = (uint16_t)(v >> 16);
        }
    }
    asm volatile("cp.async.wait_group 0;" ::: "memory");
    __syncthreads();

    // ---- QK^T : per warp 16 q-rows x 64 key-cols ----
    const int ra = lane & 15;
    const int ca = (lane >> 4) * 8;
    float acc[8][4];
#pragma unroll
    for (int ni = 0; ni < 8; ni++)
#pragma unroll
        for (int f = 0; f < 4; f++) acc[ni][f] = 0.f;

#pragma unroll
    for (int ks = 0; ks < 4; ks++) {
        uint32_t ah[4];
        uint32_t aoff = (warp_m * 16 + ra) * ARS + (ks * 16 + ca) * 2;
        ldx4(ah, sb + OFF_QH + aoff);
        uint32_t bh[4][4], bl[4][4];
#pragma unroll
        for (int pb = 0; pb < 4; pb++) {
            uint32_t boff = (warp_n * 64 + pb * 16 + ra) * ARS + (ks * 16 + ca) * 2;
            ldx4(bh[pb], sb + OFF_KH + boff);
            ldx4(bl[pb], sb + OFF_KL + boff);
        }
#pragma unroll
        for (int pb = 0; pb < 4; pb++)
#pragma unroll
            for (int hf = 0; hf < 2; hf++) {
                int ni = pb * 2 + hf;
                mma16816(acc[ni], ah, bh[pb][hf], bh[pb][hf + 2]);
                mma16816(acc[ni], ah, bl[pb][hf], bl[pb][hf + 2]);
            }
    }

    // ---- mask + softmax ----
    const int er = lane >> 2;
    const int ec = (lane & 3) * 2;
    const int iq = warp_m * 16 + er;
    const float scale = 0.125f;

#pragma unroll
    for (int ni = 0; ni < 8; ni++)
#pragma unroll
        for (int f = 0; f < 4; f++) {
            int i = iq + ((f >= 2) ? 8 : 0);
            int j = warp_n * 64 + ni * 8 + ec + (f & 1);
            bool valid = (64 + i >= j) && (nb > 0 || j >= 64);
            acc[ni][f] = valid ? acc[ni][f] * scale : -1e30f;
        }

    float m0 = -1e30f, m1 = -1e30f;
#pragma unroll
    for (int ni = 0; ni < 8; ni++) {
        m0 = fmaxf(m0, fmaxf(acc[ni][0], acc[ni][1]));
        m1 = fmaxf(m1, fmaxf(acc[ni][2], acc[ni][3]));
    }
    m0 = fmaxf(m0, __shfl_xor_sync(0xffffffffu, m0, 1));
    m0 = fmaxf(m0, __shfl_xor_sync(0xffffffffu, m0, 2));
    m1 = fmaxf(m1, __shfl_xor_sync(0xffffffffu, m1, 1));
    m1 = fmaxf(m1, __shfl_xor_sync(0xffffffffu, m1, 2));
    float* rmax = (float*)(sm + OFF_RMAX);
    if ((lane & 3) == 0) {
        rmax[iq * 2 + warp_n] = m0;
        rmax[(iq + 8) * 2 + warp_n] = m1;
    }
    __syncthreads();
    float g0 = fmaxf(rmax[iq * 2], rmax[iq * 2 + 1]);
    float g1 = fmaxf(rmax[(iq + 8) * 2], rmax[(iq + 8) * 2 + 1]);

    float s0 = 0.f, s1 = 0.f;
#pragma unroll
    for (int ni = 0; ni < 8; ni++) {
        acc[ni][0] = __expf(acc[ni][0] - g0);
        acc[ni][1] = __expf(acc[ni][1] - g0);
        acc[ni][2] = __expf(acc[ni][2] - g1);
        acc[ni][3] = __expf(acc[ni][3] - g1);
        s0 += acc[ni][0] + acc[ni][1];
        s1 += acc[ni][2] + acc[ni][3];
    }
    s0 += __shfl_xor_sync(0xffffffffu, s0, 1);
    s0 += __shfl_xor_sync(0xffffffffu, s0, 2);
    s1 += __shfl_xor_sync(0xffffffffu, s1, 1);
    s1 += __shfl_xor_sync(0xffffffffu, s1, 2);
    float* rsum = (float*)(sm + OFF_RSUM);
    if ((lane & 3) == 0) {
        rsum[iq * 2 + warp_n] = s0;
        rsum[(iq + 8) * 2 + warp_n] = s1;
    }
    __syncthreads();
    float inv0 = 1.f / (rsum[iq * 2] + rsum[iq * 2 + 1]);
    float inv1 = 1.f / (rsum[(iq + 8) * 2] + rsum[(iq + 8) * 2 + 1]);

    // write P hi (fp16) to smem
#pragma unroll
    for (int ni = 0; ni < 8; ni++) {
        int j = warp_n * 64 + ni * 8 + ec;
        *(uint32_t*)(sm + OFF_PH + iq * PRS + j * 2) =
            pack2h(acc[ni][0] * inv0, acc[ni][1] * inv0);
        *(uint32_t*)(sm + OFF_PH + (iq + 8) * PRS + j * 2) =
            pack2h(acc[ni][2] * inv1, acc[ni][3] * inv1);
    }
    __syncthreads();

    // ---- P @ V : per warp 16 q-rows x 32 d-cols ----
    float oacc[4][4];
#pragma unroll
    for (int ni = 0; ni < 4; ni++)
#pragma unroll
        for (int f = 0; f < 4; f++) oacc[ni][f] = 0.f;

#pragma unroll
    for (int ks = 0; ks < 8; ks++) {
        uint32_t ph[4];
        uint32_t aoff = (warp_m * 16 + ra) * PRS + (ks * 16 + ca) * 2;
        ldx4(ph, sb + OFF_PH + aoff);
        uint32_t vh[2][4], vl[2][4];
#pragma unroll
        for (int pb = 0; pb < 2; pb++) {
            uint32_t boff = (warp_n * 32 + pb * 16 + ra) * PRS + (ks * 16 + ca) * 2;
            ldx4(vh[pb], sb + OFF_VTH + boff);
            ldx4(vl[pb], sb + OFF_VTL + boff);
        }
#pragma unroll
        for (int pb = 0; pb < 2; pb++)
#pragma unroll
            for (int hf = 0; hf < 2; hf++) {
                int ni = pb * 2 + hf;
                mma16816(oacc[ni], ph, vh[pb][hf], vh[pb][hf + 2]);
                mma16816(oacc[ni], ph, vl[pb][hf], vl[pb][hf + 2]);
            }
    }

    // ---- epilogue: O -> global fp16 hi ----
#pragma unroll
    for (int ni = 0; ni < 4; ni++) {
        int colg = col0 + warp_n * 32 + ni * 8 + ec;
        float* d = oacc[ni];
#pragma unroll
        for (int rr = 0; rr < 2; rr++) {
            int row = qrow0 + warp_m * 16 + er + rr * 8;
            *(uint32_t*)(Oh + (size_t)row * Cv + colg) =
                pack2h(d[rr * 2 + 0], d[rr * 2 + 1]);
        }
    }
}

// ---------------------------------------------------------------------------
extern "C" void kernel_launch(void* const* d_in, const int* in_sizes, int n_in,
                              void* d_out, int out_size)
{
    const float* x  = (const float*)d_in[0];
    const float* Wq = (const float*)d_in[1];
    const float* bq = (const float*)d_in[2];
    const float* Wk = (const float*)d_in[3];
    const float* bk = (const float*)d_in[4];
    const float* Wv = (const float*)d_in[5];
    const float* bv = (const float*)d_in[6];
    const float* Wo = (const float*)d_in[7];
    const float* bo = (const float*)d_in[8];
    float* out = (float*)d_out;

    void* p;
    h16 *Xh, *Qh, *Ql, *Kh, *Kl, *Vh, *Vl, *Oh, *Wh, *Wl;
    cudaGetSymbolAddress(&p, g_Xh); Xh = (h16*)p;
    cudaGetSymbolAddress(&p, g_Qh); Qh = (h16*)p;
    cudaGetSymbolAddress(&p, g_Ql); Ql = (h16*)p;
    cudaGetSymbolAddress(&p, g_Kh); Kh = (h16*)p;
    cudaGetSymbolAddress(&p, g_Kl); Kl = (h16*)p;
    cudaGetSymbolAddress(&p, g_Vh); Vh = (h16*)p;
    cudaGetSymbolAddress(&p, g_Vl); Vl = (h16*)p;
    cudaGetSymbolAddress(&p, g_Oh); Oh = (h16*)p;
    cudaGetSymbolAddress(&p, g_Wh); Wh = (h16*)p;
    cudaGetSymbolAddress(&p, g_Wl); Wl = (h16*)p;

    cudaFuncSetAttribute(gemm_mma<0>, cudaFuncAttributeMaxDynamicSharedMemorySize, GEMM_SMEM);
    cudaFuncSetAttribute(gemm_mma<1>, cudaFuncAttributeMaxDynamicSharedMemorySize, GEMM_SMEM);
    cudaFuncSetAttribute(attn_tc, cudaFuncAttributeMaxDynamicSharedMemorySize, ATTN_SMEM);

    const size_t WSZ = (size_t)Cv * Cv;
    const int xn4 = Mv * Cv / 4;
    const int wn4 = (int)(WSZ / 4);

    split_hi<<<xn4 / 256, 256>>>(x, Xh, xn4);
    split_hilo<<<wn4 / 256, 256>>>(Wq, Wh + 0 * WSZ, Wl + 0 * WSZ, wn4);
    split_hilo<<<wn4 / 256, 256>>>(Wk, Wh + 1 * WSZ, Wl + 1 * WSZ, wn4);
    split_hilo<<<wn4 / 256, 256>>>(Wv, Wh + 2 * WSZ, Wl + 2 * WSZ, wn4);
    split_hilo<<<wn4 / 256, 256>>>(Wo, Wh + 3 * WSZ, Wl + 3 * WSZ, wn4);

    // merged QKV projection, fp16 hi/lo outputs
    dim3 gq(24, Mv / 128);
    gemm_mma<1><<<gq, 256, GEMM_SMEM>>>(Xh, Wh, Wl, bq, bk, bv,
                                        nullptr, Qh, Ql, Kh, Kl, Vh, Vl);

    // tensor-core attention -> Oh (fp16 hi only)
    dim3 ga(NBv, Hv, Bv);
    attn_tc<<<ga, 256, ATTN_SMEM>>>(Qh, Kh, Kl, Vh, Vl, Oh);

    // output projection (fp32 out)
    dim3 gg(Cv / 128, Mv / 128);
    gemm_mma<0><<<gg, 256, GEMM_SMEM>>>(Oh, Wh + 3 * WSZ, Wl + 3 * WSZ,
                                        bo, nullptr, nullptr, out,
                                        nullptr, nullptr, nullptr, nullptr,
                                        nullptr, nullptr);
}